// round 6
// baseline (speedup 1.0000x reference)
#include <cuda_runtime.h>

// CSPN 3x3 propagation (BS=16, H=352, W=1216, f32), persistent grid-stride,
// vertical 2-row pairing: each thread computes out rows (y0, y0+1) at one x4,
// sharing the 4 input rows y0-1..y0+2 between both outputs.
//   34 vec mem-ops / 8 pixels (vs 20/4) and ~1.7x per-thread MLP,
//   at 6 blocks/SM (<=42 regs) occupancy.
// Kernel tensor streams once -> __ldcs; output -> __stcs.

#define BS 16
#define H  352
#define W  1216
#define W4 (W / 4)   // 304
#define H2 (H / 2)   // 176

#define NSM    148
#define BLKSM  6
#define NBLK   (NSM * BLKSM)   // 888

__global__ __launch_bounds__(256, BLKSM) void cspn_kernel(
    const float4* __restrict__ ker4,    // [BS, 9, H, W4]
    const float4* __restrict__ inp4,    // [BS, H, W4]
    const float4* __restrict__ inp0_4,  // [BS, H, W4]
    float4*       __restrict__ out4)    // [BS, H, W4]
{
    const unsigned total  = BS * H2 * W4;           // 856,064 pair-tiles
    const unsigned stride = gridDim.x * blockDim.x; // 227,328

    const float4 z = make_float4(0.f, 0.f, 0.f, 0.f);
    const size_t ker_plane = (size_t)H * W4;

    for (unsigned tid = blockIdx.x * blockDim.x + threadIdx.x;
         tid < total; tid += stride)
    {
        unsigned x4 = tid % W4;
        unsigned yp = (tid / W4) % H2;
        unsigned b  = tid / (W4 * H2);
        unsigned y0 = yp * 2;              // even row; y0+1 always < H

        const size_t ker_base0 = (size_t)b * 9 * ker_plane + (size_t)y0 * W4 + x4;
        const size_t ker_base1 = ker_base0 + W4;
        const size_t pix0 = ((size_t)b * H + y0) * W4 + x4;
        const size_t pix1 = pix0 + W4;

        bool has_l = (x4 > 0);
        bool has_r = (x4 < W4 - 1);

        float4 acc0 = z, acc1 = z;

        // j walks the 4 input rows y0-1 .. y0+2.
        //   row j feeds acc0 via kernel tap-row j   (j = 0..2)
        //   row j feeds acc1 via kernel tap-row j-1 (j = 1..3)
#pragma unroll
        for (int j = 0; j < 4; j++) {
            int r = (int)y0 - 1 + j;
            bool vy = (r >= 0) && (r < H);
            const float4* rp = inp4 + ((size_t)b * H + (vy ? r : 0)) * W4;

            float4 lft = (vy && has_l) ? __ldg(rp + x4 - 1) : z;
            float4 mid =  vy           ? __ldg(rp + x4)     : z;
            float4 rgt = (vy && has_r) ? __ldg(rp + x4 + 1) : z;

            if (j < 3) {   // taps t = 3*j + dx for output row y0
                float4 k0 = __ldcs(&ker4[ker_base0 + (size_t)(3 * j + 0) * ker_plane]);
                float4 k1 = __ldcs(&ker4[ker_base0 + (size_t)(3 * j + 1) * ker_plane]);
                float4 k2 = __ldcs(&ker4[ker_base0 + (size_t)(3 * j + 2) * ker_plane]);
                // center tap (t=4) of row y0 sits at j==1: use input0
                float4 c = (j == 1) ? __ldg(&inp0_4[pix0]) : mid;

                acc0.x = fmaf(k0.x, lft.w, acc0.x);
                acc0.y = fmaf(k0.y, mid.x, acc0.y);
                acc0.z = fmaf(k0.z, mid.y, acc0.z);
                acc0.w = fmaf(k0.w, mid.z, acc0.w);
                acc0.x = fmaf(k1.x, c.x,   acc0.x);
                acc0.y = fmaf(k1.y, c.y,   acc0.y);
                acc0.z = fmaf(k1.z, c.z,   acc0.z);
                acc0.w = fmaf(k1.w, c.w,   acc0.w);
                acc0.x = fmaf(k2.x, mid.y, acc0.x);
                acc0.y = fmaf(k2.y, mid.z, acc0.y);
                acc0.z = fmaf(k2.z, mid.w, acc0.z);
                acc0.w = fmaf(k2.w, rgt.x, acc0.w);
            }
            if (j > 0) {   // taps t = 3*(j-1) + dx for output row y0+1
                float4 k0 = __ldcs(&ker4[ker_base1 + (size_t)(3 * (j - 1) + 0) * ker_plane]);
                float4 k1 = __ldcs(&ker4[ker_base1 + (size_t)(3 * (j - 1) + 1) * ker_plane]);
                float4 k2 = __ldcs(&ker4[ker_base1 + (size_t)(3 * (j - 1) + 2) * ker_plane]);
                // center tap (t=4) of row y0+1 sits at j==2: use input0
                float4 c = (j == 2) ? __ldg(&inp0_4[pix1]) : mid;

                acc1.x = fmaf(k0.x, lft.w, acc1.x);
                acc1.y = fmaf(k0.y, mid.x, acc1.y);
                acc1.z = fmaf(k0.z, mid.y, acc1.z);
                acc1.w = fmaf(k0.w, mid.z, acc1.w);
                acc1.x = fmaf(k1.x, c.x,   acc1.x);
                acc1.y = fmaf(k1.y, c.y,   acc1.y);
                acc1.z = fmaf(k1.z, c.z,   acc1.z);
                acc1.w = fmaf(k1.w, c.w,   acc1.w);
                acc1.x = fmaf(k2.x, mid.y, acc1.x);
                acc1.y = fmaf(k2.y, mid.z, acc1.y);
                acc1.z = fmaf(k2.z, mid.w, acc1.z);
                acc1.w = fmaf(k2.w, rgt.x, acc1.w);
            }
        }

        __stcs(&out4[pix0], acc0);
        __stcs(&out4[pix1], acc1);
    }
}

extern "C" void kernel_launch(void* const* d_in, const int* in_sizes, int n_in,
                              void* d_out, int out_size)
{
    const float4* ker4   = (const float4*)d_in[0];
    const float4* inp4   = (const float4*)d_in[1];
    const float4* inp0_4 = (const float4*)d_in[2];
    float4*       out4   = (float4*)d_out;

    cspn_kernel<<<NBLK, 256>>>(ker4, inp4, inp0_4, out4);
}

// round 7
// speedup vs baseline: 1.0468x; 1.0468x over previous
#include <cuda_runtime.h>

// CSPN 3x3 propagation (BS=16, H=352, W=1216, f32) — FINAL (R5 form).
//
// out[b,y,x] = sum_{t!=4} kernel[b,t,y,x] * input_pad[b, y+t/3-1, x+t%3-1]
//            + kernel[b,4,y,x] * input0[b,y,x]
//
// Pure HBM streamer: 328.7 MB compulsory traffic (kernel tensor 246.5 MB
// read-once dominates). Measured 43.5 us = 7.56 TB/s = 94.5% of spec.
//
// Design points (each verified by a bench round):
//  - 1 float4/thread, row-wise 3x{lft,mid,rgt} input gather: 32 regs ->
//    full 2048 threads/SM occupancy (R3/R6 showed any occ drop loses).
//  - __ldcs on the stream-once kernel tensor + __stcs stores: keep L2 for
//    the 9x-reused input rows (R2: -5.9 us).
//  - Persistent grid = 148 SMs x 8 blocks: kills wave-tail (R5: -2.3 us).

#define BS 16
#define H  352
#define W  1216
#define W4 (W / 4)   // 304

#define NSM    148
#define BLKSM  8
#define NBLK   (NSM * BLKSM)   // 1184

__global__ __launch_bounds__(256, 8) void cspn_kernel(
    const float4* __restrict__ ker4,    // [BS, 9, H, W4]
    const float4* __restrict__ inp4,    // [BS, H, W4]
    const float4* __restrict__ inp0_4,  // [BS, H, W4]
    float4*       __restrict__ out4)    // [BS, H, W4]
{
    const unsigned total  = BS * H * W4;            // 1,712,128
    const unsigned stride = gridDim.x * blockDim.x; // 303,104

    const float4 z = make_float4(0.f, 0.f, 0.f, 0.f);
    const size_t ker_plane = (size_t)H * W4;

    for (unsigned tid = blockIdx.x * blockDim.x + threadIdx.x;
         tid < total; tid += stride)
    {
        unsigned x4 = tid % W4;
        unsigned y  = (tid / W4) % H;
        unsigned b  = tid / (W4 * H);

        const size_t ker_base = (size_t)b * 9 * ker_plane + (size_t)y * W4 + x4;
        const size_t pix_base = ((size_t)b * H + y) * W4 + x4;

        bool has_l = (x4 > 0);
        bool has_r = (x4 < W4 - 1);

        float4 acc = z;

#pragma unroll
        for (int dy = 0; dy < 3; dy++) {
            int yy = (int)y + dy - 1;
            bool vy = (yy >= 0) && (yy < H);
            const float4* rp = inp4 + ((size_t)b * H + (vy ? yy : 0)) * W4;

            float4 lft = (vy && has_l) ? __ldg(rp + x4 - 1) : z;
            float4 mid =  vy           ? __ldg(rp + x4)     : z;
            float4 rgt = (vy && has_r) ? __ldg(rp + x4 + 1) : z;

            float4 k0 = __ldcs(&ker4[ker_base + (size_t)(dy * 3 + 0) * ker_plane]);
            float4 k1 = __ldcs(&ker4[ker_base + (size_t)(dy * 3 + 1) * ker_plane]);
            float4 k2 = __ldcs(&ker4[ker_base + (size_t)(dy * 3 + 2) * ker_plane]);

            // center tap (t=4): kernel * input0 instead of kernel * input
            float4 c = (dy == 1) ? __ldg(&inp0_4[pix_base]) : mid;

            // tap dx=0: cols x0-1..x0+2
            acc.x = fmaf(k0.x, lft.w, acc.x);
            acc.y = fmaf(k0.y, mid.x, acc.y);
            acc.z = fmaf(k0.z, mid.y, acc.z);
            acc.w = fmaf(k0.w, mid.z, acc.w);
            // tap dx=1 (center column): dy==1 -> input0, else input
            acc.x = fmaf(k1.x, c.x, acc.x);
            acc.y = fmaf(k1.y, c.y, acc.y);
            acc.z = fmaf(k1.z, c.z, acc.z);
            acc.w = fmaf(k1.w, c.w, acc.w);
            // tap dx=2: cols x0+1..x0+4
            acc.x = fmaf(k2.x, mid.y, acc.x);
            acc.y = fmaf(k2.y, mid.z, acc.y);
            acc.z = fmaf(k2.z, mid.w, acc.z);
            acc.w = fmaf(k2.w, rgt.x, acc.w);
        }

        __stcs(&out4[pix_base], acc);
    }
}

extern "C" void kernel_launch(void* const* d_in, const int* in_sizes, int n_in,
                              void* d_out, int out_size)
{
    const float4* ker4   = (const float4*)d_in[0];
    const float4* inp4   = (const float4*)d_in[1];
    const float4* inp0_4 = (const float4*)d_in[2];
    float4*       out4   = (float4*)d_out;

    cspn_kernel<<<NBLK, 256>>>(ker4, inp4, inp0_4, out4);
}

// round 8
// speedup vs baseline: 1.0514x; 1.0044x over previous
#include <cuda_runtime.h>

// CSPN 3x3 propagation (BS=16, H=352, W=1216, f32) — R5 form + last-use hint.
//
// out[b,y,x] = sum_{t!=4} kernel[b,t,y,x] * input_pad[b, y+t/3-1, x+t%3-1]
//            + kernel[b,4,y,x] * input0[b,y,x]
//
// Pure HBM streamer: 328.7 MB compulsory traffic. R5 measured 43.5 us =
// 7.56 TB/s = 94.5% of spec. This round: kernel-tensor loads switched from
// __ldcs (evict-first) to __ldlu (last-use) — the data is dead after one
// read, so let L2 drop the lines immediately instead of aging them.
//
// Verified design points:
//  - 1 float4/thread, 32 regs -> full 2048 threads/SM (R3/R6: occ drops lose).
//  - streaming hints on kernel/output keep L2 for 9x-reused input (R2: -5.9us).
//  - persistent grid 148x8 blocks kills wave-tail (R5: -2.3us).

#define BS 16
#define H  352
#define W  1216
#define W4 (W / 4)   // 304

#define NSM    148
#define BLKSM  8
#define NBLK   (NSM * BLKSM)   // 1184

__global__ __launch_bounds__(256, 8) void cspn_kernel(
    const float4* __restrict__ ker4,    // [BS, 9, H, W4]
    const float4* __restrict__ inp4,    // [BS, H, W4]
    const float4* __restrict__ inp0_4,  // [BS, H, W4]
    float4*       __restrict__ out4)    // [BS, H, W4]
{
    const unsigned total  = BS * H * W4;            // 1,712,128
    const unsigned stride = gridDim.x * blockDim.x; // 303,104

    const float4 z = make_float4(0.f, 0.f, 0.f, 0.f);
    const size_t ker_plane = (size_t)H * W4;

    for (unsigned tid = blockIdx.x * blockDim.x + threadIdx.x;
         tid < total; tid += stride)
    {
        unsigned x4 = tid % W4;
        unsigned y  = (tid / W4) % H;
        unsigned b  = tid / (W4 * H);

        const size_t ker_base = (size_t)b * 9 * ker_plane + (size_t)y * W4 + x4;
        const size_t pix_base = ((size_t)b * H + y) * W4 + x4;

        bool has_l = (x4 > 0);
        bool has_r = (x4 < W4 - 1);

        float4 acc = z;

#pragma unroll
        for (int dy = 0; dy < 3; dy++) {
            int yy = (int)y + dy - 1;
            bool vy = (yy >= 0) && (yy < H);
            const float4* rp = inp4 + ((size_t)b * H + (vy ? yy : 0)) * W4;

            float4 lft = (vy && has_l) ? __ldg(rp + x4 - 1) : z;
            float4 mid =  vy           ? __ldg(rp + x4)     : z;
            float4 rgt = (vy && has_r) ? __ldg(rp + x4 + 1) : z;

            // kernel tensor: read exactly once -> last-use hint
            float4 k0 = __ldlu(&ker4[ker_base + (size_t)(dy * 3 + 0) * ker_plane]);
            float4 k1 = __ldlu(&ker4[ker_base + (size_t)(dy * 3 + 1) * ker_plane]);
            float4 k2 = __ldlu(&ker4[ker_base + (size_t)(dy * 3 + 2) * ker_plane]);

            // center tap (t=4): kernel * input0 instead of kernel * input
            float4 c = (dy == 1) ? __ldg(&inp0_4[pix_base]) : mid;

            // tap dx=0: cols x0-1..x0+2
            acc.x = fmaf(k0.x, lft.w, acc.x);
            acc.y = fmaf(k0.y, mid.x, acc.y);
            acc.z = fmaf(k0.z, mid.y, acc.z);
            acc.w = fmaf(k0.w, mid.z, acc.w);
            // tap dx=1 (center column): dy==1 -> input0, else input
            acc.x = fmaf(k1.x, c.x, acc.x);
            acc.y = fmaf(k1.y, c.y, acc.y);
            acc.z = fmaf(k1.z, c.z, acc.z);
            acc.w = fmaf(k1.w, c.w, acc.w);
            // tap dx=2: cols x0+1..x0+4
            acc.x = fmaf(k2.x, mid.y, acc.x);
            acc.y = fmaf(k2.y, mid.z, acc.y);
            acc.z = fmaf(k2.z, mid.w, acc.z);
            acc.w = fmaf(k2.w, rgt.x, acc.w);
        }

        __stcs(&out4[pix_base], acc);
    }
}

extern "C" void kernel_launch(void* const* d_in, const int* in_sizes, int n_in,
                              void* d_out, int out_size)
{
    const float4* ker4   = (const float4*)d_in[0];
    const float4* inp4   = (const float4*)d_in[1];
    const float4* inp0_4 = (const float4*)d_in[2];
    float4*       out4   = (float4*)d_out;

    cspn_kernel<<<NBLK, 256>>>(ker4, inp4, inp0_4, out4);
}

// round 9
// speedup vs baseline: 1.0537x; 1.0022x over previous
#include <cuda_runtime.h>

// CSPN 3x3 propagation (BS=16, H=352, W=1216, f32) — converged streamer.
//
// out[b,y,x] = sum_{t!=4} kernel[b,t,y,x] * input_pad[b, y+t/3-1, x+t%3-1]
//            + kernel[b,4,y,x] * input0[b,y,x]
//
// Pure HBM-bound: 328.7 MB compulsory traffic, measured ~43.5 us =
// ~7.55 TB/s = ~94% of 8 TB/s spec (floor 41.1 us). Verified design points:
//  - 1 float4/thread, 32 regs -> full 2048 threads/SM occupancy
//    (R3/R6: any occupancy drop costs more than per-thread MLP gains).
//  - __ldcs on stream-once kernel tensor + __stcs stores preserve L2 for
//    the 9x-reused input rows (R2: -5.9 us). __ldlu was neutral (R8).
//  - persistent grid sized to exactly one resident wave kills the
//    wave-tail (R5: -2.3 us). This round: 592 blocks x 512 threads
//    (same occupancy, fewer scheduling units).

#define BS 16
#define H  352
#define W  1216
#define W4 (W / 4)   // 304

#define NSM     148
#define THREADS 512
#define BLKSM   4
#define NBLK    (NSM * BLKSM)   // 592

__global__ __launch_bounds__(THREADS, BLKSM) void cspn_kernel(
    const float4* __restrict__ ker4,    // [BS, 9, H, W4]
    const float4* __restrict__ inp4,    // [BS, H, W4]
    const float4* __restrict__ inp0_4,  // [BS, H, W4]
    float4*       __restrict__ out4)    // [BS, H, W4]
{
    const unsigned total  = BS * H * W4;            // 1,712,128
    const unsigned stride = gridDim.x * blockDim.x; // 303,104

    const float4 z = make_float4(0.f, 0.f, 0.f, 0.f);
    const size_t ker_plane = (size_t)H * W4;

    for (unsigned tid = blockIdx.x * blockDim.x + threadIdx.x;
         tid < total; tid += stride)
    {
        unsigned x4 = tid % W4;
        unsigned y  = (tid / W4) % H;
        unsigned b  = tid / (W4 * H);

        const size_t ker_base = (size_t)b * 9 * ker_plane + (size_t)y * W4 + x4;
        const size_t pix_base = ((size_t)b * H + y) * W4 + x4;

        bool has_l = (x4 > 0);
        bool has_r = (x4 < W4 - 1);

        float4 acc = z;

#pragma unroll
        for (int dy = 0; dy < 3; dy++) {
            int yy = (int)y + dy - 1;
            bool vy = (yy >= 0) && (yy < H);
            const float4* rp = inp4 + ((size_t)b * H + (vy ? yy : 0)) * W4;

            float4 lft = (vy && has_l) ? __ldg(rp + x4 - 1) : z;
            float4 mid =  vy           ? __ldg(rp + x4)     : z;
            float4 rgt = (vy && has_r) ? __ldg(rp + x4 + 1) : z;

            // kernel tensor: read exactly once -> evict-first streaming
            float4 k0 = __ldcs(&ker4[ker_base + (size_t)(dy * 3 + 0) * ker_plane]);
            float4 k1 = __ldcs(&ker4[ker_base + (size_t)(dy * 3 + 1) * ker_plane]);
            float4 k2 = __ldcs(&ker4[ker_base + (size_t)(dy * 3 + 2) * ker_plane]);

            // center tap (t=4): kernel * input0 instead of kernel * input
            float4 c = (dy == 1) ? __ldg(&inp0_4[pix_base]) : mid;

            // tap dx=0: cols x0-1..x0+2
            acc.x = fmaf(k0.x, lft.w, acc.x);
            acc.y = fmaf(k0.y, mid.x, acc.y);
            acc.z = fmaf(k0.z, mid.y, acc.z);
            acc.w = fmaf(k0.w, mid.z, acc.w);
            // tap dx=1 (center column): dy==1 -> input0, else input
            acc.x = fmaf(k1.x, c.x, acc.x);
            acc.y = fmaf(k1.y, c.y, acc.y);
            acc.z = fmaf(k1.z, c.z, acc.z);
            acc.w = fmaf(k1.w, c.w, acc.w);
            // tap dx=2: cols x0+1..x0+4
            acc.x = fmaf(k2.x, mid.y, acc.x);
            acc.y = fmaf(k2.y, mid.z, acc.y);
            acc.z = fmaf(k2.z, mid.w, acc.z);
            acc.w = fmaf(k2.w, rgt.x, acc.w);
        }

        __stcs(&out4[pix_base], acc);
    }
}

extern "C" void kernel_launch(void* const* d_in, const int* in_sizes, int n_in,
                              void* d_out, int out_size)
{
    const float4* ker4   = (const float4*)d_in[0];
    const float4* inp4   = (const float4*)d_in[1];
    const float4* inp0_4 = (const float4*)d_in[2];
    float4*       out4   = (float4*)d_out;

    cspn_kernel<<<NBLK, THREADS>>>(ker4, inp4, inp0_4, out4);
}